// round 9
// baseline (speedup 1.0000x reference)
#include <cuda_runtime.h>

// LSTM char-RNN, fully fused single persistent kernel.
//   inputs [1024,256] i32, kernel Wx [128,1024] f32, recurrent R [256,1024] f32,
//   bias [1024] f32, dense_w [256,128] f32, dense_b [128] f32
//   out = softmax(h_T @ dense_w + dense_b)  -> [1024,128] f32
//
// Grid: 128 CTAs x 256 threads. CTA owns 8 batch rows; thread owns 1 unit
// (4 gates x 8 rows = 32 fp32 accumulators, packed as 16 f32x2).
// h lives in SMEM (k-major [unit][row]), c lives in registers. No cross-CTA
// communication, no global state, one launch.

#define BATCHN   1024
#define SEQLEN   256
#define UNITSN   256
#define NCHARS   128
#define BT       8
#define NCTA     (BATCHN / BT)   // 128
#define NTHR     256
#define FOURU    (4 * UNITSN)    // 1024

#define FMA2(acc, a, b) \
    asm("fma.rn.f32x2 %0, %1, %2, %0;" : "+l"(acc) : "l"(a), "l"(b))

__device__ __forceinline__ unsigned long long bcast2(float v) {
    unsigned long long r;
    unsigned u = __float_as_uint(v);
    asm("mov.b64 %0, {%1, %1};" : "=l"(r) : "r"(u));
    return r;
}

__device__ __forceinline__ unsigned long long pack2(float lo, float hi) {
    unsigned long long r;
    unsigned a = __float_as_uint(lo), b = __float_as_uint(hi);
    asm("mov.b64 %0, {%1, %2};" : "=l"(r) : "r"(a), "r"(b));
    return r;
}

__device__ __forceinline__ void unpack2(unsigned long long v, float& lo, float& hi) {
    unsigned a, b;
    asm("mov.b64 {%0, %1}, %2;" : "=r"(a), "=r"(b) : "l"(v));
    lo = __uint_as_float(a);
    hi = __uint_as_float(b);
}

// exp-based activations: ex2.approx (+rcp) keeps per-step rel error ~1e-6,
// which stays ~4e-6 after the 1/(1-f) recurrence amplification. tanh.approx
// (~1e-3) would NOT survive the 1e-3 output threshold.
__device__ __forceinline__ float fast_sigmoid(float x) {
    return __fdividef(1.0f, 1.0f + __expf(-x));
}
__device__ __forceinline__ float fast_tanh(float x) {
    float e = __expf(2.0f * x);            // inf for large x -> result 1, ok
    return 1.0f - __fdividef(2.0f, e + 1.0f);
}

// 4 k-values of the recurrent GEMM: acc2[g][p] += h[k][2p..2p+1] * R[k][g*U+tid]
// (h pairs are 64-bit SMEM broadcasts, R values pre-staged in buf registers).
__device__ __forceinline__ void compute_chunk(
    unsigned long long (&acc2)[4][BT / 2],
    const float (&buf)[16],
    const float (*h_s)[BT],       // [unit][row]
    int k0)
{
#pragma unroll
    for (int kk = 0; kk < 4; ++kk) {
        const unsigned long long* hp =
            (const unsigned long long*)(&h_s[k0 + kk][0]);
        unsigned long long h0 = hp[0], h1 = hp[1], h2 = hp[2], h3 = hp[3];
#pragma unroll
        for (int g = 0; g < 4; ++g) {
            unsigned long long rv = bcast2(buf[kk * 4 + g]);
            FMA2(acc2[g][0], h0, rv);
            FMA2(acc2[g][1], h1, rv);
            FMA2(acc2[g][2], h2, rv);
            FMA2(acc2[g][3], h3, rv);
        }
    }
}

// Stage 16 R values (4 k x 4 gates) for one chunk into registers.
__device__ __forceinline__ void load_chunk(
    float (&buf)[16], const float* __restrict__ Rbase, int kc)
{
    const float* p = Rbase + kc * (4 * FOURU);
#pragma unroll
    for (int kk = 0; kk < 4; ++kk)
#pragma unroll
        for (int g = 0; g < 4; ++g)
            buf[kk * 4 + g] = p[kk * FOURU + g * UNITSN];
}

__global__ void __launch_bounds__(NTHR, 1) lstm_fused_kernel(
    const int*   __restrict__ inp,
    const float* __restrict__ Wx,
    const float* __restrict__ R,
    const float* __restrict__ bias,
    const float* __restrict__ Wd,
    const float* __restrict__ bd,
    float*       __restrict__ out)
{
    __shared__ __align__(16) float h_s[UNITSN][BT];   // [unit][row], 8 KB
    __shared__ int idx_s[BT];

    const int tid = threadIdx.x;          // unit index 0..255
    const int b0  = blockIdx.x * BT;      // first batch row of this CTA

    // h0 = 0
    for (int i = tid; i < UNITSN * BT; i += NTHR)
        ((float*)h_s)[i] = 0.0f;

    float c_reg[BT];
#pragma unroll
    for (int r = 0; r < BT; ++r) c_reg[r] = 0.0f;

    float bia[4];
#pragma unroll
    for (int g = 0; g < 4; ++g) bia[g] = bias[g * UNITSN + tid];

    const float* Rbase = R + tid;   // column base for this unit; +g*UNITSN per gate

    for (int t = 0; t < SEQLEN; ++t) {
        if (tid < BT) idx_s[tid] = inp[(b0 + tid) * SEQLEN + t];
        __syncthreads();   // idx visible; also orders previous step's h_s writes

        // z init: x_proj gather + bias  (Wx is 512 KB, L2-resident; 128 hot rows)
        float accf[4][BT];
#pragma unroll
        for (int r = 0; r < BT; ++r) {
            const float* wrow = Wx + idx_s[r] * FOURU + tid;
#pragma unroll
            for (int g = 0; g < 4; ++g)
                accf[g][r] = wrow[g * UNITSN] + bia[g];
        }
        unsigned long long acc2[4][BT / 2];
#pragma unroll
        for (int g = 0; g < 4; ++g)
#pragma unroll
            for (int p = 0; p < BT / 2; ++p)
                acc2[g][p] = pack2(accf[g][2 * p], accf[g][2 * p + 1]);

        // ---- K loop: z += h @ R, chunks of 4 k, double-buffered R prefetch ----
        float ra[16], rb[16];
        load_chunk(ra, Rbase, 0);

        for (int kc = 0; kc < 64; kc += 2) {
            load_chunk(rb, Rbase, kc + 1);          // kc+1 <= 63, always valid
            compute_chunk(acc2, ra, h_s, kc * 4);
            if (kc + 2 < 64) load_chunk(ra, Rbase, kc + 2);
            compute_chunk(acc2, rb, h_s, (kc + 1) * 4);
        }

        // ---- gates + state update (registers only) ----
        float hv[BT];
#pragma unroll
        for (int p = 0; p < BT / 2; ++p) {
            float zi0, zi1, zf0, zf1, zg0, zg1, zo0, zo1;
            unpack2(acc2[0][p], zi0, zi1);
            unpack2(acc2[1][p], zf0, zf1);
            unpack2(acc2[2][p], zg0, zg1);
            unpack2(acc2[3][p], zo0, zo1);
            {
                float i = fast_sigmoid(zi0), f = fast_sigmoid(zf0);
                float g = fast_tanh(zg0),    o = fast_sigmoid(zo0);
                float c = f * c_reg[2 * p] + i * g;
                c_reg[2 * p] = c;
                hv[2 * p] = o * fast_tanh(c);
            }
            {
                float i = fast_sigmoid(zi1), f = fast_sigmoid(zf1);
                float g = fast_tanh(zg1),    o = fast_sigmoid(zo1);
                float c = f * c_reg[2 * p + 1] + i * g;
                c_reg[2 * p + 1] = c;
                hv[2 * p + 1] = o * fast_tanh(c);
            }
        }

        __syncthreads();   // everyone done reading h_s for this step
#pragma unroll
        for (int r = 0; r < BT; ++r) h_s[tid][r] = hv[r];
    }
    __syncthreads();       // final h visible to all warps

    // ---- dense + softmax: warp w handles batch row b0+w, lane handles 4 cols ----
    const int w = tid >> 5;
    const int l = tid & 31;

    float4 bb = ((const float4*)bd)[l];
    float a0 = bb.x, a1 = bb.y, a2 = bb.z, a3 = bb.w;
#pragma unroll 4
    for (int u = 0; u < UNITSN; ++u) {
        float hvv = h_s[u][w];                                  // warp broadcast
        float4 wv = *(const float4*)(Wd + u * NCHARS + 4 * l);  // coalesced
        a0 += hvv * wv.x; a1 += hvv * wv.y;
        a2 += hvv * wv.z; a3 += hvv * wv.w;
    }
    float m = fmaxf(fmaxf(a0, a1), fmaxf(a2, a3));
#pragma unroll
    for (int off = 16; off; off >>= 1)
        m = fmaxf(m, __shfl_xor_sync(0xffffffffu, m, off));
    float e0 = __expf(a0 - m), e1 = __expf(a1 - m);
    float e2 = __expf(a2 - m), e3 = __expf(a3 - m);
    float s = e0 + e1 + e2 + e3;
#pragma unroll
    for (int off = 16; off; off >>= 1)
        s += __shfl_xor_sync(0xffffffffu, s, off);
    float inv = 1.0f / s;
    *(float4*)(out + (b0 + w) * NCHARS + 4 * l) =
        make_float4(e0 * inv, e1 * inv, e2 * inv, e3 * inv);
}

extern "C" void kernel_launch(void* const* d_in, const int* in_sizes, int n_in,
                              void* d_out, int out_size)
{
    const int*   inp  = (const int*)d_in[0];    // [1024, 256]
    const float* Wx   = (const float*)d_in[1];  // [128, 1024]
    const float* R    = (const float*)d_in[2];  // [256, 1024]
    const float* bias = (const float*)d_in[3];  // [1024]
    const float* Wd   = (const float*)d_in[4];  // [256, 128]
    const float* bd   = (const float*)d_in[5];  // [128]
    float*       out  = (float*)d_out;          // [1024, 128]

    lstm_fused_kernel<<<NCTA, NTHR>>>(inp, Wx, R, bias, Wd, bd, out);
}